// round 11
// baseline (speedup 1.0000x reference)
#include <cuda_runtime.h>
#include <cuda_bf16.h>
#include <cuda_fp16.h>
#include <cstdint>

// CuGraphSAGEConv pipeline (3 kernels) — R9 config + deeper gather MLP:
//   K0 convert: x(f32) -> g_xh(fp16) + feat x hi/lo(bf16); W -> g_wcvt hi/lo
//   K1 gather:  8-lane groups, 16-edge main loop (16 value loads in flight),
//               HADD2 trees + f32 accum -> feat agg hi/lo
//   K2 gemm:    multi-tile double-buffered cp.async + mma.sync 3-pass bf16

#define D_IN  64
#define DK    128
#define D_OUT 64

#define NPAD  100352
// feat row (512B): [agg_hi 128B | x_hi 128B | agg_lo 128B | x_lo 128B]
__device__ unsigned char g_feat[(size_t)NPAD * 512];
__device__ __half        g_xh[(size_t)NPAD * D_IN];
__device__ unsigned char g_wcvt[64 * 512];

// ======================= helpers =======================
__device__ __forceinline__ uint32_t smem_u32(const void* p) {
    uint32_t a;
    asm("{ .reg .u64 t; cvta.to.shared.u64 t, %1; cvt.u32.u64 %0, t; }"
        : "=r"(a) : "l"(p));
    return a;
}
__device__ __forceinline__ uint2 split2(float v0, float v1) {
    __nv_bfloat16 h0 = __float2bfloat16_rn(v0);
    __nv_bfloat16 h1 = __float2bfloat16_rn(v1);
    float r0 = v0 - __bfloat162float(h0);
    float r1 = v1 - __bfloat162float(h1);
    __nv_bfloat162 hh = __halves2bfloat162(h0, h1);
    __nv_bfloat162 ll = __halves2bfloat162(__float2bfloat16_rn(r0),
                                           __float2bfloat16_rn(r1));
    uint2 r;
    r.x = *reinterpret_cast<uint32_t*>(&hh);
    r.y = *reinterpret_cast<uint32_t*>(&ll);
    return r;
}
__device__ __forceinline__ void ldm_x4(uint4& r, uint32_t addr) {
    asm volatile("ldmatrix.sync.aligned.m8n8.x4.shared.b16 {%0,%1,%2,%3}, [%4];"
                 : "=r"(r.x), "=r"(r.y), "=r"(r.z), "=r"(r.w) : "r"(addr));
}
__device__ __forceinline__ void mma16816(float* c, const uint4& a,
                                         uint32_t b0, uint32_t b1) {
    asm volatile(
        "mma.sync.aligned.m16n8k16.row.col.f32.bf16.bf16.f32 "
        "{%0,%1,%2,%3}, {%4,%5,%6,%7}, {%8,%9}, {%0,%1,%2,%3};"
        : "+f"(c[0]), "+f"(c[1]), "+f"(c[2]), "+f"(c[3])
        : "r"(a.x), "r"(a.y), "r"(a.z), "r"(a.w), "r"(b0), "r"(b1));
}
__device__ __forceinline__ void cp16(uint32_t dst, const void* src) {
    asm volatile("cp.async.cg.shared.global [%0], [%1], 16;"
                 :: "r"(dst), "l"(src));
}
__device__ __forceinline__ __half2 u2h(uint32_t u) {
    return *reinterpret_cast<__half2*>(&u);
}
// 4-value HADD2 tree -> f32 accumulate
__device__ __forceinline__ void tree4(float* acc, const uint4& v0, const uint4& v1,
                                      const uint4& v2, const uint4& v3) {
    __half2 s0 = __hadd2(__hadd2(u2h(v0.x), u2h(v1.x)), __hadd2(u2h(v2.x), u2h(v3.x)));
    __half2 s1 = __hadd2(__hadd2(u2h(v0.y), u2h(v1.y)), __hadd2(u2h(v2.y), u2h(v3.y)));
    __half2 s2 = __hadd2(__hadd2(u2h(v0.z), u2h(v1.z)), __hadd2(u2h(v2.z), u2h(v3.z)));
    __half2 s3 = __hadd2(__hadd2(u2h(v0.w), u2h(v1.w)), __hadd2(u2h(v2.w), u2h(v3.w)));
    float2 f;
    f = __half22float2(s0); acc[0] += f.x; acc[1] += f.y;
    f = __half22float2(s1); acc[2] += f.x; acc[3] += f.y;
    f = __half22float2(s2); acc[4] += f.x; acc[5] += f.y;
    f = __half22float2(s3); acc[6] += f.x; acc[7] += f.y;
}

// ======================= K0: convert x and W =======================
#define XBLOCKS 6272       // NPAD*16/256

__global__ __launch_bounds__(256)
void convert_kernel(const float4* __restrict__ x4,
                    const float4* __restrict__ W4, int N)
{
    if (blockIdx.x >= XBLOCKS) {
        const int idx = (blockIdx.x - XBLOCKS) * 256 + threadIdx.x;  // 0..2047
        const int o = idx >> 5;
        const int q = idx & 31;
        float4 v = __ldg(W4 + idx);
        uint2 p0 = split2(v.x, v.y);
        uint2 p1 = split2(v.z, v.w);
        unsigned char* wr = g_wcvt + (size_t)o * 512;
        *reinterpret_cast<uint2*>(wr + q * 8)       = make_uint2(p0.x, p1.x);
        *reinterpret_cast<uint2*>(wr + 256 + q * 8) = make_uint2(p0.y, p1.y);
        return;
    }
    const int idx  = blockIdx.x * 256 + threadIdx.x;
    const int node = idx >> 4;
    const int gl   = idx & 15;

    float4 v = make_float4(0.f, 0.f, 0.f, 0.f);
    if (node < N) v = __ldg(x4 + (size_t)node * 16 + gl);

    __half2 h01 = __floats2half2_rn(v.x, v.y);
    __half2 h23 = __floats2half2_rn(v.z, v.w);
    uint2 hp;
    hp.x = *reinterpret_cast<uint32_t*>(&h01);
    hp.y = *reinterpret_cast<uint32_t*>(&h23);
    reinterpret_cast<uint2*>(g_xh)[(size_t)node * 16 + gl] = hp;

    uint2 p0 = split2(v.x, v.y);
    uint2 p1 = split2(v.z, v.w);
    unsigned char* fr = g_feat + (size_t)node * 512;
    *reinterpret_cast<uint2*>(fr + 128 + gl * 8) = make_uint2(p0.x, p1.x);
    *reinterpret_cast<uint2*>(fr + 384 + gl * 8) = make_uint2(p0.y, p1.y);
}

// ======================= K1: gather =======================
__global__ __launch_bounds__(256)
void gather_kernel(const int* __restrict__ row,
                   const int* __restrict__ colptr,
                   int N)
{
    const int g  = (blockIdx.x * 256 + threadIdx.x) >> 3;
    const int gl = threadIdx.x & 7;
    if (g >= N) return;

    const uint4* xh4 = reinterpret_cast<const uint4*>(g_xh);

    const int e0 = __ldg(colptr + g);
    const int e1 = __ldg(colptr + g + 1);

    float acc[8];
    #pragma unroll
    for (int i = 0; i < 8; i++) acc[i] = 0.f;

    int e = e0;
    // 16-edge main loop: four independent 4-trees, 16 value loads in flight
    if (e + 16 <= e1) {
        int s[16];
        #pragma unroll
        for (int j = 0; j < 16; j++) s[j] = __ldg(row + e + j);
        e += 16;
        while (true) {
            const bool more = (e + 16 <= e1);
            int t[16];
            if (more) {
                #pragma unroll
                for (int j = 0; j < 16; j++) t[j] = __ldg(row + e + j);
            }
            uint4 v[16];
            #pragma unroll
            for (int j = 0; j < 16; j++)
                v[j] = __ldg(xh4 + (size_t)s[j] * 8 + gl);
            tree4(acc, v[0],  v[1],  v[2],  v[3]);
            tree4(acc, v[4],  v[5],  v[6],  v[7]);
            tree4(acc, v[8],  v[9],  v[10], v[11]);
            tree4(acc, v[12], v[13], v[14], v[15]);
            if (!more) break;
            #pragma unroll
            for (int j = 0; j < 16; j++) s[j] = t[j];
            e += 16;
        }
    }
    if (e + 8 <= e1) {          // at most once (remainder < 16)
        int s[8];
        #pragma unroll
        for (int j = 0; j < 8; j++) s[j] = __ldg(row + e + j);
        uint4 v[8];
        #pragma unroll
        for (int j = 0; j < 8; j++)
            v[j] = __ldg(xh4 + (size_t)s[j] * 8 + gl);
        tree4(acc, v[0], v[1], v[2], v[3]);
        tree4(acc, v[4], v[5], v[6], v[7]);
        e += 8;
    }
    if (e + 4 <= e1) {          // at most once (remainder < 8)
        int s0 = __ldg(row + e), s1 = __ldg(row + e + 1);
        int s2 = __ldg(row + e + 2), s3 = __ldg(row + e + 3);
        uint4 v0 = __ldg(xh4 + (size_t)s0 * 8 + gl);
        uint4 v1 = __ldg(xh4 + (size_t)s1 * 8 + gl);
        uint4 v2 = __ldg(xh4 + (size_t)s2 * 8 + gl);
        uint4 v3 = __ldg(xh4 + (size_t)s3 * 8 + gl);
        tree4(acc, v0, v1, v2, v3);
        e += 4;
    }
    for (; e < e1; e++) {
        int s = __ldg(row + e);
        uint4 v = __ldg(xh4 + (size_t)s * 8 + gl);
        float2 f;
        f = __half22float2(u2h(v.x)); acc[0] += f.x; acc[1] += f.y;
        f = __half22float2(u2h(v.y)); acc[2] += f.x; acc[3] += f.y;
        f = __half22float2(u2h(v.z)); acc[4] += f.x; acc[5] += f.y;
        f = __half22float2(u2h(v.w)); acc[6] += f.x; acc[7] += f.y;
    }

    const int deg = e1 - e0;
    const float inv = 1.f / (float)(deg > 0 ? deg : 1);
    #pragma unroll
    for (int i = 0; i < 8; i++) acc[i] *= inv;

    uint2 p0 = split2(acc[0], acc[1]);
    uint2 p1 = split2(acc[2], acc[3]);
    uint2 p2 = split2(acc[4], acc[5]);
    uint2 p3 = split2(acc[6], acc[7]);
    unsigned char* fr = g_feat + (size_t)g * 512;
    *reinterpret_cast<uint4*>(fr + gl * 16)       = make_uint4(p0.x, p1.x, p2.x, p3.x);
    *reinterpret_cast<uint4*>(fr + 256 + gl * 16) = make_uint4(p0.y, p1.y, p2.y, p3.y);
}

// ======================= K2: pipelined HMMA GEMM =======================
#define TB     64        // nodes per tile
#define ROWB   272
#define SM_WHI 0
#define SM_WLO 17408
#define SM_A0  34816     // buffer 0: [AHI 17408 | ALO 17408]
#define SM_A1  69632     // buffer 1
#define SM_TOT 104448
#define GRID2  296       // 2 CTAs/SM * 148

extern __shared__ char g_sm[];

__device__ __forceinline__ void stage_tile(uint32_t sb, int buf, int tbase, int tid)
{
    const uint32_t abase = sb + (buf ? SM_A1 : SM_A0);
    #pragma unroll
    for (int j = 0; j < 8; j++) {
        const int c   = tid + 256 * j;      // 0..2047
        const int r   = c >> 5;             // row 0..63
        const int q   = c & 31;             // 0..15 hi, 16..31 lo
        const unsigned char* src = g_feat + (size_t)(tbase + r) * 512 + q * 16;
        const uint32_t dst = abase + (q < 16 ? 0 : 17408)
                             + r * ROWB + (q & 15) * 16;
        cp16(dst, src);
    }
    asm volatile("cp.async.commit_group;" ::: "memory");
}

__global__ __launch_bounds__(256, 2)
void gemm_mma_kernel(const float* __restrict__ b,
                     float*       __restrict__ out,
                     int N, int ntiles)
{
    const uint32_t sb = smem_u32(g_sm);
    const int tid  = threadIdx.x;
    const int wid  = tid >> 5;
    const int lane = tid & 31;

    // ---- stage W (once per block) ----
    #pragma unroll
    for (int j = 0; j < 8; j++) {
        const int c = tid + 256 * j;
        const int o = c >> 5;
        const int q = c & 31;
        const unsigned char* src = g_wcvt + (size_t)o * 512 + q * 16;
        const uint32_t dst = sb + (q < 16 ? SM_WHI : SM_WLO)
                             + o * ROWB + (q & 15) * 16;
        cp16(dst, src);
    }
    asm volatile("cp.async.commit_group;" ::: "memory");

    int t0 = blockIdx.x;
    if (t0 < ntiles) stage_tile(sb, 0, t0 * TB, tid);

    const int wm = wid >> 1;
    const int wn = wid & 1;

    const uint32_t a_off = (uint32_t)(wm * 16 + (lane & 15)) * ROWB
                           + (uint32_t)(lane >> 4) * 16;
    const int brow = wn * 32 + ((lane >> 4) << 3) + (lane & 7);
    const uint32_t b_base = sb + SM_WHI
        + (uint32_t)brow * ROWB + (uint32_t)((lane >> 3) & 1) * 16;

    const int g   = lane >> 2;
    const int tig = lane & 3;
    float2 bb[4];
    #pragma unroll
    for (int ns = 0; ns < 4; ns++) {
        int col = wn * 32 + ns * 8 + 2 * tig;
        bb[ns] = make_float2(__ldg(b + col), __ldg(b + col + 1));
    }

    int i = 0;
    for (int t = t0; t < ntiles; t += GRID2, i++) {
        const int nxt = t + GRID2;
        if (nxt < ntiles) {
            stage_tile(sb, (i + 1) & 1, nxt * TB, tid);
            asm volatile("cp.async.wait_group 1;" ::: "memory");
        } else {
            asm volatile("cp.async.wait_group 0;" ::: "memory");
        }
        __syncthreads();

        const uint32_t a_base = sb + ((i & 1) ? SM_A1 : SM_A0) + a_off;

        float acc[4][4];
        #pragma unroll
        for (int ns = 0; ns < 4; ns++)
            #pragma unroll
            for (int q = 0; q < 4; q++) acc[ns][q] = 0.f;

        #pragma unroll
        for (int ks = 0; ks < 8; ks++) {
            const uint32_t ao = a_base + ks * 32;
            const uint32_t bo = b_base + ks * 32;
            uint4 ah, al, bh0, bh1, bl0, bl1;
            ldm_x4(ah, ao);
            ldm_x4(al, ao + 17408);
            ldm_x4(bh0, bo);
            ldm_x4(bh1, bo + 16 * ROWB);
            ldm_x4(bl0, bo + (SM_WLO - SM_WHI));
            ldm_x4(bl1, bo + (SM_WLO - SM_WHI) + 16 * ROWB);

            mma16816(acc[0], ah, bh0.x, bh0.y);
            mma16816(acc[1], ah, bh0.z, bh0.w);
            mma16816(acc[2], ah, bh1.x, bh1.y);
            mma16816(acc[3], ah, bh1.z, bh1.w);

            mma16816(acc[0], ah, bl0.x, bl0.y);
            mma16816(acc[1], ah, bl0.z, bl0.w);
            mma16816(acc[2], ah, bl1.x, bl1.y);
            mma16816(acc[3], ah, bl1.z, bl1.w);

            mma16816(acc[0], al, bh0.x, bh0.y);
            mma16816(acc[1], al, bh0.z, bh0.w);
            mma16816(acc[2], al, bh1.x, bh1.y);
            mma16816(acc[3], al, bh1.z, bh1.w);
        }

        const int node0 = t * TB + wm * 16 + g;
        const int node1 = node0 + 8;
        #pragma unroll
        for (int ns = 0; ns < 4; ns++) {
            const int col = wn * 32 + ns * 8 + 2 * tig;
            if (node0 < N)
                *reinterpret_cast<float2*>(out + (size_t)node0 * D_OUT + col) =
                    make_float2(acc[ns][0] + bb[ns].x, acc[ns][1] + bb[ns].y);
            if (node1 < N)
                *reinterpret_cast<float2*>(out + (size_t)node1 * D_OUT + col) =
                    make_float2(acc[ns][2] + bb[ns].x, acc[ns][3] + bb[ns].y);
        }
        __syncthreads();
    }
}

// ======================= launch =======================
extern "C" void kernel_launch(void* const* d_in, const int* in_sizes, int n_in,
                              void* d_out, int out_size)
{
    const float* x      = (const float*)d_in[0];
    const int*   row    = (const int*)  d_in[1];
    const int*   colptr = (const int*)  d_in[2];
    const float* W      = (const float*)d_in[3];
    const float* b      = (const float*)d_in[4];
    float*       out    = (float*)d_out;

    const int N = in_sizes[2] - 1;   // 100000
    const int ntiles = (N + TB - 1) / TB;

    cudaFuncSetAttribute(gemm_mma_kernel,
                         cudaFuncAttributeMaxDynamicSharedMemorySize, SM_TOT);

    convert_kernel<<<XBLOCKS + 8, 256>>>(
        reinterpret_cast<const float4*>(x),
        reinterpret_cast<const float4*>(W), N);

    gather_kernel<<<(N * 8 + 255) / 256, 256>>>(row, colptr, N);

    gemm_mma_kernel<<<GRID2, 256, SM_TOT>>>(b, out, N, ntiles);
}

// round 12
// speedup vs baseline: 1.0295x; 1.0295x over previous
#include <cuda_runtime.h>
#include <cuda_bf16.h>
#include <cuda_fp16.h>
#include <cstdint>

// CuGraphSAGEConv pipeline — R9 config + degree-binned gather order:
//   memset:    zero 64 degree-bucket counters
//   K0 convert: x -> g_xh(fp16) + feat x hi/lo(bf16); W -> g_wcvt hi/lo;
//               + per-node degree bucket/rank (two-level atomic)
//   K0b scatter: build g_perm (nodes grouped by degree bucket)
//   K1 gather:  8-lane groups over perm order (co-warp nodes have ~equal deg)
//   K2 gemm:    multi-tile double-buffered cp.async + mma.sync 3-pass bf16

#define D_IN  64
#define DK    128
#define D_OUT 64

#define NPAD  100352
// feat row (512B): [agg_hi 128B | x_hi 128B | agg_lo 128B | x_lo 128B]
__device__ unsigned char g_feat[(size_t)NPAD * 512];
__device__ __half        g_xh[(size_t)NPAD * D_IN];
__device__ unsigned char g_wcvt[64 * 512];
__device__ int           g_cnt[64];
__device__ unsigned int  g_rankb[NPAD];
__device__ int           g_perm[NPAD];

// ======================= helpers =======================
__device__ __forceinline__ uint32_t smem_u32(const void* p) {
    uint32_t a;
    asm("{ .reg .u64 t; cvta.to.shared.u64 t, %1; cvt.u32.u64 %0, t; }"
        : "=r"(a) : "l"(p));
    return a;
}
__device__ __forceinline__ uint2 split2(float v0, float v1) {
    __nv_bfloat16 h0 = __float2bfloat16_rn(v0);
    __nv_bfloat16 h1 = __float2bfloat16_rn(v1);
    float r0 = v0 - __bfloat162float(h0);
    float r1 = v1 - __bfloat162float(h1);
    __nv_bfloat162 hh = __halves2bfloat162(h0, h1);
    __nv_bfloat162 ll = __halves2bfloat162(__float2bfloat16_rn(r0),
                                           __float2bfloat16_rn(r1));
    uint2 r;
    r.x = *reinterpret_cast<uint32_t*>(&hh);
    r.y = *reinterpret_cast<uint32_t*>(&ll);
    return r;
}
__device__ __forceinline__ void ldm_x4(uint4& r, uint32_t addr) {
    asm volatile("ldmatrix.sync.aligned.m8n8.x4.shared.b16 {%0,%1,%2,%3}, [%4];"
                 : "=r"(r.x), "=r"(r.y), "=r"(r.z), "=r"(r.w) : "r"(addr));
}
__device__ __forceinline__ void mma16816(float* c, const uint4& a,
                                         uint32_t b0, uint32_t b1) {
    asm volatile(
        "mma.sync.aligned.m16n8k16.row.col.f32.bf16.bf16.f32 "
        "{%0,%1,%2,%3}, {%4,%5,%6,%7}, {%8,%9}, {%0,%1,%2,%3};"
        : "+f"(c[0]), "+f"(c[1]), "+f"(c[2]), "+f"(c[3])
        : "r"(a.x), "r"(a.y), "r"(a.z), "r"(a.w), "r"(b0), "r"(b1));
}
__device__ __forceinline__ void cp16(uint32_t dst, const void* src) {
    asm volatile("cp.async.cg.shared.global [%0], [%1], 16;"
                 :: "r"(dst), "l"(src));
}
__device__ __forceinline__ __half2 u2h(uint32_t u) {
    return *reinterpret_cast<__half2*>(&u);
}
// 4-value HADD2 tree -> f32 accumulate
__device__ __forceinline__ void tree4(float* acc, const uint4& v0, const uint4& v1,
                                      const uint4& v2, const uint4& v3) {
    __half2 s0 = __hadd2(__hadd2(u2h(v0.x), u2h(v1.x)), __hadd2(u2h(v2.x), u2h(v3.x)));
    __half2 s1 = __hadd2(__hadd2(u2h(v0.y), u2h(v1.y)), __hadd2(u2h(v2.y), u2h(v3.y)));
    __half2 s2 = __hadd2(__hadd2(u2h(v0.z), u2h(v1.z)), __hadd2(u2h(v2.z), u2h(v3.z)));
    __half2 s3 = __hadd2(__hadd2(u2h(v0.w), u2h(v1.w)), __hadd2(u2h(v2.w), u2h(v3.w)));
    float2 f;
    f = __half22float2(s0); acc[0] += f.x; acc[1] += f.y;
    f = __half22float2(s1); acc[2] += f.x; acc[3] += f.y;
    f = __half22float2(s2); acc[4] += f.x; acc[5] += f.y;
    f = __half22float2(s3); acc[6] += f.x; acc[7] += f.y;
}

// ======================= K0: convert x, W + degree count =======================
#define XBLOCKS 6272       // NPAD*16/256
#define CBLOCKS 392        // NPAD/256

__global__ __launch_bounds__(256)
void convert_kernel(const float4* __restrict__ x4,
                    const float4* __restrict__ W4,
                    const int*    __restrict__ colptr, int N)
{
    if (blockIdx.x >= XBLOCKS + 8) {
        // degree-count path: 1 thread per node, two-level rank
        __shared__ int lcnt[64];
        __shared__ int lbase[64];
        const int tid = threadIdx.x;
        if (tid < 64) lcnt[tid] = 0;
        __syncthreads();
        const int n = (blockIdx.x - XBLOCKS - 8) * 256 + tid;
        int b = 0, lrank = 0;
        if (n < N) {
            const int deg = __ldg(colptr + n + 1) - __ldg(colptr + n);
            b = min(deg >> 2, 63);
            lrank = atomicAdd(&lcnt[b], 1);
        }
        __syncthreads();
        if (tid < 64 && lcnt[tid] > 0)
            lbase[tid] = atomicAdd(&g_cnt[tid], lcnt[tid]);
        __syncthreads();
        if (n < N)
            g_rankb[n] = ((unsigned)b << 24) | (unsigned)(lbase[b] + lrank);
        return;
    }
    if (blockIdx.x >= XBLOCKS) {
        const int idx = (blockIdx.x - XBLOCKS) * 256 + threadIdx.x;  // 0..2047
        const int o = idx >> 5;
        const int q = idx & 31;
        float4 v = __ldg(W4 + idx);
        uint2 p0 = split2(v.x, v.y);
        uint2 p1 = split2(v.z, v.w);
        unsigned char* wr = g_wcvt + (size_t)o * 512;
        *reinterpret_cast<uint2*>(wr + q * 8)       = make_uint2(p0.x, p1.x);
        *reinterpret_cast<uint2*>(wr + 256 + q * 8) = make_uint2(p0.y, p1.y);
        return;
    }
    const int idx  = blockIdx.x * 256 + threadIdx.x;
    const int node = idx >> 4;
    const int gl   = idx & 15;

    float4 v = make_float4(0.f, 0.f, 0.f, 0.f);
    if (node < N) v = __ldg(x4 + (size_t)node * 16 + gl);

    __half2 h01 = __floats2half2_rn(v.x, v.y);
    __half2 h23 = __floats2half2_rn(v.z, v.w);
    uint2 hp;
    hp.x = *reinterpret_cast<uint32_t*>(&h01);
    hp.y = *reinterpret_cast<uint32_t*>(&h23);
    reinterpret_cast<uint2*>(g_xh)[(size_t)node * 16 + gl] = hp;

    uint2 p0 = split2(v.x, v.y);
    uint2 p1 = split2(v.z, v.w);
    unsigned char* fr = g_feat + (size_t)node * 512;
    *reinterpret_cast<uint2*>(fr + 128 + gl * 8) = make_uint2(p0.x, p1.x);
    *reinterpret_cast<uint2*>(fr + 384 + gl * 8) = make_uint2(p0.y, p1.y);
}

// ======================= K0b: scatter perm =======================
__global__ __launch_bounds__(256)
void scatter_kernel(int N)
{
    __shared__ int soff[64];
    const int tid = threadIdx.x;
    if (tid < 64) {
        // exclusive prefix of g_cnt (64 values; serial per thread is fine)
        int off = 0;
        for (int i = 0; i < 64; i++) {
            if (i == tid) break;
            off += g_cnt[i];
        }
        soff[tid] = off;
    }
    __syncthreads();
    const int n = blockIdx.x * 256 + tid;
    if (n >= N) return;
    const unsigned rb = g_rankb[n];
    const int b    = rb >> 24;
    const int rank = rb & 0xFFFFFF;
    g_perm[soff[b] + rank] = n;
}

// ======================= K1: gather (perm order) =======================
__global__ __launch_bounds__(256)
void gather_kernel(const int* __restrict__ row,
                   const int* __restrict__ colptr,
                   int N)
{
    const int gi = (blockIdx.x * 256 + threadIdx.x) >> 3;
    const int gl = threadIdx.x & 7;
    if (gi >= N) return;
    const int g = __ldg(g_perm + gi);

    const uint4* xh4 = reinterpret_cast<const uint4*>(g_xh);

    const int e0 = __ldg(colptr + g);
    const int e1 = __ldg(colptr + g + 1);

    float acc[8];
    #pragma unroll
    for (int i = 0; i < 8; i++) acc[i] = 0.f;

    int e = e0;
    if (e + 8 <= e1) {
        int s[8];
        #pragma unroll
        for (int j = 0; j < 8; j++) s[j] = __ldg(row + e + j);
        e += 8;
        while (true) {
            const bool more = (e + 8 <= e1);
            int t[8];
            if (more) {
                #pragma unroll
                for (int j = 0; j < 8; j++) t[j] = __ldg(row + e + j);
            }
            uint4 v0 = __ldg(xh4 + (size_t)s[0] * 8 + gl);
            uint4 v1 = __ldg(xh4 + (size_t)s[1] * 8 + gl);
            uint4 v2 = __ldg(xh4 + (size_t)s[2] * 8 + gl);
            uint4 v3 = __ldg(xh4 + (size_t)s[3] * 8 + gl);
            uint4 v4 = __ldg(xh4 + (size_t)s[4] * 8 + gl);
            uint4 v5 = __ldg(xh4 + (size_t)s[5] * 8 + gl);
            uint4 v6 = __ldg(xh4 + (size_t)s[6] * 8 + gl);
            uint4 v7 = __ldg(xh4 + (size_t)s[7] * 8 + gl);
            tree4(acc, v0, v1, v2, v3);
            tree4(acc, v4, v5, v6, v7);
            if (!more) break;
            #pragma unroll
            for (int j = 0; j < 8; j++) s[j] = t[j];
            e += 8;
        }
    }
    if (e + 4 <= e1) {
        int s0 = __ldg(row + e), s1 = __ldg(row + e + 1);
        int s2 = __ldg(row + e + 2), s3 = __ldg(row + e + 3);
        uint4 v0 = __ldg(xh4 + (size_t)s0 * 8 + gl);
        uint4 v1 = __ldg(xh4 + (size_t)s1 * 8 + gl);
        uint4 v2 = __ldg(xh4 + (size_t)s2 * 8 + gl);
        uint4 v3 = __ldg(xh4 + (size_t)s3 * 8 + gl);
        tree4(acc, v0, v1, v2, v3);
        e += 4;
    }
    for (; e < e1; e++) {
        int s = __ldg(row + e);
        uint4 v = __ldg(xh4 + (size_t)s * 8 + gl);
        float2 f;
        f = __half22float2(u2h(v.x)); acc[0] += f.x; acc[1] += f.y;
        f = __half22float2(u2h(v.y)); acc[2] += f.x; acc[3] += f.y;
        f = __half22float2(u2h(v.z)); acc[4] += f.x; acc[5] += f.y;
        f = __half22float2(u2h(v.w)); acc[6] += f.x; acc[7] += f.y;
    }

    const int deg = e1 - e0;
    const float inv = 1.f / (float)(deg > 0 ? deg : 1);
    #pragma unroll
    for (int i = 0; i < 8; i++) acc[i] *= inv;

    uint2 p0 = split2(acc[0], acc[1]);
    uint2 p1 = split2(acc[2], acc[3]);
    uint2 p2 = split2(acc[4], acc[5]);
    uint2 p3 = split2(acc[6], acc[7]);
    unsigned char* fr = g_feat + (size_t)g * 512;
    *reinterpret_cast<uint4*>(fr + gl * 16)       = make_uint4(p0.x, p1.x, p2.x, p3.x);
    *reinterpret_cast<uint4*>(fr + 256 + gl * 16) = make_uint4(p0.y, p1.y, p2.y, p3.y);
}

// ======================= K2: pipelined HMMA GEMM =======================
#define TB     64        // nodes per tile
#define ROWB   272
#define SM_WHI 0
#define SM_WLO 17408
#define SM_A0  34816     // buffer 0: [AHI 17408 | ALO 17408]
#define SM_A1  69632     // buffer 1
#define SM_TOT 104448
#define GRID2  296

extern __shared__ char g_sm[];

__device__ __forceinline__ void stage_tile(uint32_t sb, int buf, int tbase, int tid)
{
    const uint32_t abase = sb + (buf ? SM_A1 : SM_A0);
    #pragma unroll
    for (int j = 0; j < 8; j++) {
        const int c   = tid + 256 * j;      // 0..2047
        const int r   = c >> 5;             // row 0..63
        const int q   = c & 31;             // 0..15 hi, 16..31 lo
        const unsigned char* src = g_feat + (size_t)(tbase + r) * 512 + q * 16;
        const uint32_t dst = abase + (q < 16 ? 0 : 17408)
                             + r * ROWB + (q & 15) * 16;
        cp16(dst, src);
    }
    asm volatile("cp.async.commit_group;" ::: "memory");
}

__global__ __launch_bounds__(256, 2)
void gemm_mma_kernel(const float* __restrict__ b,
                     float*       __restrict__ out,
                     int N, int ntiles)
{
    const uint32_t sb = smem_u32(g_sm);
    const int tid  = threadIdx.x;
    const int wid  = tid >> 5;
    const int lane = tid & 31;

    // ---- stage W (once per block) ----
    #pragma unroll
    for (int j = 0; j < 8; j++) {
        const int c = tid + 256 * j;
        const int o = c >> 5;
        const int q = c & 31;
        const unsigned char* src = g_wcvt + (size_t)o * 512 + q * 16;
        const uint32_t dst = sb + (q < 16 ? SM_WHI : SM_WLO)
                             + o * ROWB + (q & 15) * 16;
        cp16(dst, src);
    }
    asm volatile("cp.async.commit_group;" ::: "memory");

    int t0 = blockIdx.x;
    if (t0 < ntiles) stage_tile(sb, 0, t0 * TB, tid);

    const int wm = wid >> 1;
    const int wn = wid & 1;

    const uint32_t a_off = (uint32_t)(wm * 16 + (lane & 15)) * ROWB
                           + (uint32_t)(lane >> 4) * 16;
    const int brow = wn * 32 + ((lane >> 4) << 3) + (lane & 7);
    const uint32_t b_base = sb + SM_WHI
        + (uint32_t)brow * ROWB + (uint32_t)((lane >> 3) & 1) * 16;

    const int g   = lane >> 2;
    const int tig = lane & 3;
    float2 bb[4];
    #pragma unroll
    for (int ns = 0; ns < 4; ns++) {
        int col = wn * 32 + ns * 8 + 2 * tig;
        bb[ns] = make_float2(__ldg(b + col), __ldg(b + col + 1));
    }

    int i = 0;
    for (int t = t0; t < ntiles; t += GRID2, i++) {
        const int nxt = t + GRID2;
        if (nxt < ntiles) {
            stage_tile(sb, (i + 1) & 1, nxt * TB, tid);
            asm volatile("cp.async.wait_group 1;" ::: "memory");
        } else {
            asm volatile("cp.async.wait_group 0;" ::: "memory");
        }
        __syncthreads();

        const uint32_t a_base = sb + ((i & 1) ? SM_A1 : SM_A0) + a_off;

        float acc[4][4];
        #pragma unroll
        for (int ns = 0; ns < 4; ns++)
            #pragma unroll
            for (int q = 0; q < 4; q++) acc[ns][q] = 0.f;

        #pragma unroll
        for (int ks = 0; ks < 8; ks++) {
            const uint32_t ao = a_base + ks * 32;
            const uint32_t bo = b_base + ks * 32;
            uint4 ah, al, bh0, bh1, bl0, bl1;
            ldm_x4(ah, ao);
            ldm_x4(al, ao + 17408);
            ldm_x4(bh0, bo);
            ldm_x4(bh1, bo + 16 * ROWB);
            ldm_x4(bl0, bo + (SM_WLO - SM_WHI));
            ldm_x4(bl1, bo + (SM_WLO - SM_WHI) + 16 * ROWB);

            mma16816(acc[0], ah, bh0.x, bh0.y);
            mma16816(acc[1], ah, bh0.z, bh0.w);
            mma16816(acc[2], ah, bh1.x, bh1.y);
            mma16816(acc[3], ah, bh1.z, bh1.w);

            mma16816(acc[0], ah, bl0.x, bl0.y);
            mma16816(acc[1], ah, bl0.z, bl0.w);
            mma16816(acc[2], ah, bl1.x, bl1.y);
            mma16816(acc[3], ah, bl1.z, bl1.w);

            mma16816(acc[0], al, bh0.x, bh0.y);
            mma16816(acc[1], al, bh0.z, bh0.w);
            mma16816(acc[2], al, bh1.x, bh1.y);
            mma16816(acc[3], al, bh1.z, bh1.w);
        }

        const int node0 = t * TB + wm * 16 + g;
        const int node1 = node0 + 8;
        #pragma unroll
        for (int ns = 0; ns < 4; ns++) {
            const int col = wn * 32 + ns * 8 + 2 * tig;
            if (node0 < N)
                *reinterpret_cast<float2*>(out + (size_t)node0 * D_OUT + col) =
                    make_float2(acc[ns][0] + bb[ns].x, acc[ns][1] + bb[ns].y);
            if (node1 < N)
                *reinterpret_cast<float2*>(out + (size_t)node1 * D_OUT + col) =
                    make_float2(acc[ns][2] + bb[ns].x, acc[ns][3] + bb[ns].y);
        }
        __syncthreads();
    }
}

// ======================= launch =======================
extern "C" void kernel_launch(void* const* d_in, const int* in_sizes, int n_in,
                              void* d_out, int out_size)
{
    const float* x      = (const float*)d_in[0];
    const int*   row    = (const int*)  d_in[1];
    const int*   colptr = (const int*)  d_in[2];
    const float* W      = (const float*)d_in[3];
    const float* b      = (const float*)d_in[4];
    float*       out    = (float*)d_out;

    const int N = in_sizes[2] - 1;   // 100000
    const int ntiles = (N + TB - 1) / TB;

    cudaFuncSetAttribute(gemm_mma_kernel,
                         cudaFuncAttributeMaxDynamicSharedMemorySize, SM_TOT);

    void* cntp = nullptr;
    cudaGetSymbolAddress(&cntp, g_cnt);
    cudaMemsetAsync(cntp, 0, 64 * sizeof(int));

    convert_kernel<<<XBLOCKS + 8 + CBLOCKS, 256>>>(
        reinterpret_cast<const float4*>(x),
        reinterpret_cast<const float4*>(W), colptr, N);

    scatter_kernel<<<CBLOCKS, 256>>>(N);

    gather_kernel<<<(N * 8 + 255) / 256, 256>>>(row, colptr, N);

    gemm_mma_kernel<<<GRID2, 256, SM_TOT>>>(b, out, N, ntiles);
}

// round 13
// speedup vs baseline: 1.3624x; 1.3233x over previous
#include <cuda_runtime.h>
#include <cuda_fp16.h>
#include <cstdint>

// CuGraphSAGEConv pipeline (3 kernels, fp16 A / split-fp16 W):
//   K0 convert: x(f32) -> g_xh(fp16); W(f32) -> g_wcvt fp16 hi/lo
//   K1 gather:  8-lane groups, 8-edge dual-tree HADD2, f32 accum -> g_agg fp16
//   K2 gemm:    128-node tiles, double-buffered cp.async (A from g_agg+g_xh),
//               mma.sync f16 2-pass (A*Whi + A*Wlo), fp32 accum, +bias

#define D_IN  64
#define DK    128
#define D_OUT 64

#define NPAD  100352
__device__ unsigned char g_agg[(size_t)NPAD * 128];   // fp16 agg row (128B)
__device__ __half        g_xh[(size_t)NPAD * D_IN];   // fp16 x row (128B)
__device__ unsigned char g_wcvt[64 * 512];            // [whi 256B | wlo 256B]/row

// ======================= helpers =======================
__device__ __forceinline__ uint32_t smem_u32(const void* p) {
    uint32_t a;
    asm("{ .reg .u64 t; cvta.to.shared.u64 t, %1; cvt.u32.u64 %0, t; }"
        : "=r"(a) : "l"(p));
    return a;
}
// two floats -> {fp16x2 hi, fp16x2 lo}
__device__ __forceinline__ uint2 split2h(float v0, float v1) {
    __half h0 = __float2half_rn(v0);
    __half h1 = __float2half_rn(v1);
    float r0 = v0 - __half2float(h0);
    float r1 = v1 - __half2float(h1);
    __half2 hh = __halves2half2(h0, h1);
    __half2 ll = __halves2half2(__float2half_rn(r0), __float2half_rn(r1));
    uint2 r;
    r.x = *reinterpret_cast<uint32_t*>(&hh);
    r.y = *reinterpret_cast<uint32_t*>(&ll);
    return r;
}
__device__ __forceinline__ void ldm_x4(uint4& r, uint32_t addr) {
    asm volatile("ldmatrix.sync.aligned.m8n8.x4.shared.b16 {%0,%1,%2,%3}, [%4];"
                 : "=r"(r.x), "=r"(r.y), "=r"(r.z), "=r"(r.w) : "r"(addr));
}
__device__ __forceinline__ void mma16816h(float* c, const uint4& a,
                                          uint32_t b0, uint32_t b1) {
    asm volatile(
        "mma.sync.aligned.m16n8k16.row.col.f32.f16.f16.f32 "
        "{%0,%1,%2,%3}, {%4,%5,%6,%7}, {%8,%9}, {%0,%1,%2,%3};"
        : "+f"(c[0]), "+f"(c[1]), "+f"(c[2]), "+f"(c[3])
        : "r"(a.x), "r"(a.y), "r"(a.z), "r"(a.w), "r"(b0), "r"(b1));
}
__device__ __forceinline__ void cp16(uint32_t dst, const void* src) {
    asm volatile("cp.async.cg.shared.global [%0], [%1], 16;"
                 :: "r"(dst), "l"(src));
}
__device__ __forceinline__ __half2 u2h(uint32_t u) {
    return *reinterpret_cast<__half2*>(&u);
}
__device__ __forceinline__ void tree4(float* acc, const uint4& v0, const uint4& v1,
                                      const uint4& v2, const uint4& v3) {
    __half2 s0 = __hadd2(__hadd2(u2h(v0.x), u2h(v1.x)), __hadd2(u2h(v2.x), u2h(v3.x)));
    __half2 s1 = __hadd2(__hadd2(u2h(v0.y), u2h(v1.y)), __hadd2(u2h(v2.y), u2h(v3.y)));
    __half2 s2 = __hadd2(__hadd2(u2h(v0.z), u2h(v1.z)), __hadd2(u2h(v2.z), u2h(v3.z)));
    __half2 s3 = __hadd2(__hadd2(u2h(v0.w), u2h(v1.w)), __hadd2(u2h(v2.w), u2h(v3.w)));
    float2 f;
    f = __half22float2(s0); acc[0] += f.x; acc[1] += f.y;
    f = __half22float2(s1); acc[2] += f.x; acc[3] += f.y;
    f = __half22float2(s2); acc[4] += f.x; acc[5] += f.y;
    f = __half22float2(s3); acc[6] += f.x; acc[7] += f.y;
}

// ======================= K0: convert x and W =======================
__global__ __launch_bounds__(256)
void convert_kernel(const float4* __restrict__ x4,
                    const float4* __restrict__ W4, int nx)
{
    const int idx = blockIdx.x * 256 + threadIdx.x;
    if (idx < nx) {
        float4 v = __ldg(x4 + idx);
        __half2 h01 = __floats2half2_rn(v.x, v.y);
        __half2 h23 = __floats2half2_rn(v.z, v.w);
        uint2 hp;
        hp.x = *reinterpret_cast<uint32_t*>(&h01);
        hp.y = *reinterpret_cast<uint32_t*>(&h23);
        reinterpret_cast<uint2*>(g_xh)[idx] = hp;
    } else if (idx < nx + 2048) {
        const int c = idx - nx;               // 0..2047
        const int o = c >> 5;
        const int q = c & 31;
        float4 v = __ldg(W4 + c);
        uint2 p0 = split2h(v.x, v.y);
        uint2 p1 = split2h(v.z, v.w);
        unsigned char* wr = g_wcvt + (size_t)o * 512;
        *reinterpret_cast<uint2*>(wr + q * 8)       = make_uint2(p0.x, p1.x);
        *reinterpret_cast<uint2*>(wr + 256 + q * 8) = make_uint2(p0.y, p1.y);
    }
}

// ======================= K1: gather =======================
__global__ __launch_bounds__(256)
void gather_kernel(const int* __restrict__ row,
                   const int* __restrict__ colptr,
                   int N)
{
    const int g  = (blockIdx.x * 256 + threadIdx.x) >> 3;
    const int gl = threadIdx.x & 7;
    if (g >= N) return;

    const uint4* xh4 = reinterpret_cast<const uint4*>(g_xh);

    const int e0 = __ldg(colptr + g);
    const int e1 = __ldg(colptr + g + 1);

    float acc[8];
    #pragma unroll
    for (int i = 0; i < 8; i++) acc[i] = 0.f;

    int e = e0;
    if (e + 8 <= e1) {
        int s[8];
        #pragma unroll
        for (int j = 0; j < 8; j++) s[j] = __ldg(row + e + j);
        e += 8;
        while (true) {
            const bool more = (e + 8 <= e1);
            int t[8];
            if (more) {
                #pragma unroll
                for (int j = 0; j < 8; j++) t[j] = __ldg(row + e + j);
            }
            uint4 v0 = __ldg(xh4 + (size_t)s[0] * 8 + gl);
            uint4 v1 = __ldg(xh4 + (size_t)s[1] * 8 + gl);
            uint4 v2 = __ldg(xh4 + (size_t)s[2] * 8 + gl);
            uint4 v3 = __ldg(xh4 + (size_t)s[3] * 8 + gl);
            uint4 v4 = __ldg(xh4 + (size_t)s[4] * 8 + gl);
            uint4 v5 = __ldg(xh4 + (size_t)s[5] * 8 + gl);
            uint4 v6 = __ldg(xh4 + (size_t)s[6] * 8 + gl);
            uint4 v7 = __ldg(xh4 + (size_t)s[7] * 8 + gl);
            tree4(acc, v0, v1, v2, v3);
            tree4(acc, v4, v5, v6, v7);
            if (!more) break;
            #pragma unroll
            for (int j = 0; j < 8; j++) s[j] = t[j];
            e += 8;
        }
    }
    if (e + 4 <= e1) {
        int s0 = __ldg(row + e), s1 = __ldg(row + e + 1);
        int s2 = __ldg(row + e + 2), s3 = __ldg(row + e + 3);
        uint4 v0 = __ldg(xh4 + (size_t)s0 * 8 + gl);
        uint4 v1 = __ldg(xh4 + (size_t)s1 * 8 + gl);
        uint4 v2 = __ldg(xh4 + (size_t)s2 * 8 + gl);
        uint4 v3 = __ldg(xh4 + (size_t)s3 * 8 + gl);
        tree4(acc, v0, v1, v2, v3);
        e += 4;
    }
    for (; e < e1; e++) {
        int s = __ldg(row + e);
        uint4 v = __ldg(xh4 + (size_t)s * 8 + gl);
        float2 f;
        f = __half22float2(u2h(v.x)); acc[0] += f.x; acc[1] += f.y;
        f = __half22float2(u2h(v.y)); acc[2] += f.x; acc[3] += f.y;
        f = __half22float2(u2h(v.z)); acc[4] += f.x; acc[5] += f.y;
        f = __half22float2(u2h(v.w)); acc[6] += f.x; acc[7] += f.y;
    }

    const int deg = e1 - e0;
    const float inv = 1.f / (float)(deg > 0 ? deg : 1);
    #pragma unroll
    for (int i = 0; i < 8; i++) acc[i] *= inv;

    __half2 h0 = __floats2half2_rn(acc[0], acc[1]);
    __half2 h1 = __floats2half2_rn(acc[2], acc[3]);
    __half2 h2 = __floats2half2_rn(acc[4], acc[5]);
    __half2 h3 = __floats2half2_rn(acc[6], acc[7]);
    uint4 o4 = make_uint4(*reinterpret_cast<uint32_t*>(&h0),
                          *reinterpret_cast<uint32_t*>(&h1),
                          *reinterpret_cast<uint32_t*>(&h2),
                          *reinterpret_cast<uint32_t*>(&h3));
    *reinterpret_cast<uint4*>(g_agg + (size_t)g * 128 + gl * 16) = o4;
}

// ======================= K2: pipelined HMMA GEMM =======================
#define TB     128       // nodes per tile
#define ROWB   272
#define SM_WHI 0
#define SM_WLO 17408
#define SM_A0  34816     // A buffer 0: 128 rows x 272B
#define SM_A1  69632     // A buffer 1
#define SM_TOT 104448
#define GRID2  296

extern __shared__ char g_sm[];

__device__ __forceinline__ void stage_tile(uint32_t sb, int buf, int tbase, int tid)
{
    const uint32_t abase = sb + (buf ? SM_A1 : SM_A0);
    #pragma unroll
    for (int j = 0; j < 8; j++) {
        const int c = tid + 256 * j;        // 0..2047
        const int r = c >> 4;               // row 0..127
        const int q = c & 15;               // chunk: 0..7 agg, 8..15 x
        const unsigned char* src = (q < 8)
            ? g_agg + (size_t)(tbase + r) * 128 + q * 16
            : reinterpret_cast<const unsigned char*>(g_xh)
              + (size_t)(tbase + r) * 128 + (q - 8) * 16;
        cp16(abase + r * ROWB + q * 16, src);
    }
    asm volatile("cp.async.commit_group;" ::: "memory");
}

__global__ __launch_bounds__(256, 2)
void gemm_mma_kernel(const float* __restrict__ b,
                     float*       __restrict__ out,
                     int N, int ntiles)
{
    const uint32_t sb = smem_u32(g_sm);
    const int tid  = threadIdx.x;
    const int wid  = tid >> 5;
    const int lane = tid & 31;

    // ---- stage W hi/lo (once per block) ----
    #pragma unroll
    for (int j = 0; j < 8; j++) {
        const int c = tid + 256 * j;        // 0..2047
        const int o = c >> 5;
        const int q = c & 31;               // 0..15 hi, 16..31 lo
        const unsigned char* src = g_wcvt + (size_t)o * 512 + q * 16;
        const uint32_t dst = sb + (q < 16 ? SM_WHI : SM_WLO)
                             + o * ROWB + (q & 15) * 16;
        cp16(dst, src);
    }
    asm volatile("cp.async.commit_group;" ::: "memory");

    int t0 = blockIdx.x;
    if (t0 < ntiles) stage_tile(sb, 0, t0 * TB, tid);

    // warp grid: 4 m-warps (32 nodes each) x 2 n-warps (32 cols each)
    const int wm = wid >> 1;
    const int wn = wid & 1;

    const uint32_t a_off = (uint32_t)(wm * 32 + (lane & 15)) * ROWB
                           + (uint32_t)(lane >> 4) * 16;
    const int brow = wn * 32 + ((lane >> 4) << 3) + (lane & 7);
    const uint32_t b_base = sb + SM_WHI
        + (uint32_t)brow * ROWB + (uint32_t)((lane >> 3) & 1) * 16;

    const int g   = lane >> 2;
    const int tig = lane & 3;
    float2 bb[4];
    #pragma unroll
    for (int ns = 0; ns < 4; ns++) {
        int col = wn * 32 + ns * 8 + 2 * tig;
        bb[ns] = make_float2(__ldg(b + col), __ldg(b + col + 1));
    }

    int i = 0;
    for (int t = t0; t < ntiles; t += GRID2, i++) {
        const int nxt = t + GRID2;
        if (nxt < ntiles) {
            stage_tile(sb, (i + 1) & 1, nxt * TB, tid);
            asm volatile("cp.async.wait_group 1;" ::: "memory");
        } else {
            asm volatile("cp.async.wait_group 0;" ::: "memory");
        }
        __syncthreads();

        const uint32_t a_base = sb + ((i & 1) ? SM_A1 : SM_A0) + a_off;

        float acc[2][4][4];
        #pragma unroll
        for (int ms = 0; ms < 2; ms++)
            #pragma unroll
            for (int ns = 0; ns < 4; ns++)
                #pragma unroll
                for (int q = 0; q < 4; q++) acc[ms][ns][q] = 0.f;

        #pragma unroll
        for (int ks = 0; ks < 8; ks++) {
            const uint32_t ao = a_base + ks * 32;
            const uint32_t bo = b_base + ks * 32;
            uint4 ah0, ah1, bh0, bh1, bl0, bl1;
            ldm_x4(ah0, ao);
            ldm_x4(ah1, ao + 16 * ROWB);
            ldm_x4(bh0, bo);
            ldm_x4(bh1, bo + 16 * ROWB);
            ldm_x4(bl0, bo + (SM_WLO - SM_WHI));
            ldm_x4(bl1, bo + (SM_WLO - SM_WHI) + 16 * ROWB);

            // pass 1: A * Whi
            mma16816h(acc[0][0], ah0, bh0.x, bh0.y);
            mma16816h(acc[0][1], ah0, bh0.z, bh0.w);
            mma16816h(acc[0][2], ah0, bh1.x, bh1.y);
            mma16816h(acc[0][3], ah0, bh1.z, bh1.w);
            mma16816h(acc[1][0], ah1, bh0.x, bh0.y);
            mma16816h(acc[1][1], ah1, bh0.z, bh0.w);
            mma16816h(acc[1][2], ah1, bh1.x, bh1.y);
            mma16816h(acc[1][3], ah1, bh1.z, bh1.w);
            // pass 2: A * Wlo
            mma16816h(acc[0][0], ah0, bl0.x, bl0.y);
            mma16816h(acc[0][1], ah0, bl0.z, bl0.w);
            mma16816h(acc[0][2], ah0, bl1.x, bl1.y);
            mma16816h(acc[0][3], ah0, bl1.z, bl1.w);
            mma16816h(acc[1][0], ah1, bl0.x, bl0.y);
            mma16816h(acc[1][1], ah1, bl0.z, bl0.w);
            mma16816h(acc[1][2], ah1, bl1.x, bl1.y);
            mma16816h(acc[1][3], ah1, bl1.z, bl1.w);
        }

        #pragma unroll
        for (int ms = 0; ms < 2; ms++) {
            const int node0 = t * TB + wm * 32 + ms * 16 + g;
            const int node1 = node0 + 8;
            #pragma unroll
            for (int ns = 0; ns < 4; ns++) {
                const int col = wn * 32 + ns * 8 + 2 * tig;
                if (node0 < N)
                    *reinterpret_cast<float2*>(out + (size_t)node0 * D_OUT + col) =
                        make_float2(acc[ms][ns][0] + bb[ns].x,
                                    acc[ms][ns][1] + bb[ns].y);
                if (node1 < N)
                    *reinterpret_cast<float2*>(out + (size_t)node1 * D_OUT + col) =
                        make_float2(acc[ms][ns][2] + bb[ns].x,
                                    acc[ms][ns][3] + bb[ns].y);
            }
        }
        __syncthreads();
    }
}

// ======================= launch =======================
extern "C" void kernel_launch(void* const* d_in, const int* in_sizes, int n_in,
                              void* d_out, int out_size)
{
    const float* x      = (const float*)d_in[0];
    const int*   row    = (const int*)  d_in[1];
    const int*   colptr = (const int*)  d_in[2];
    const float* W      = (const float*)d_in[3];
    const float* b      = (const float*)d_in[4];
    float*       out    = (float*)d_out;

    const int N = in_sizes[2] - 1;   // 100000
    const int ntiles = (N + TB - 1) / TB;

    cudaFuncSetAttribute(gemm_mma_kernel,
                         cudaFuncAttributeMaxDynamicSharedMemorySize, SM_TOT);

    const int nx = N * 16;
    convert_kernel<<<(nx + 2048 + 255) / 256, 256>>>(
        reinterpret_cast<const float4*>(x),
        reinterpret_cast<const float4*>(W), nx);

    gather_kernel<<<(N * 8 + 255) / 256, 256>>>(row, colptr, N);

    gemm_mma_kernel<<<GRID2, 256, SM_TOT>>>(b, out, N, ntiles);
}

// round 14
// speedup vs baseline: 1.4637x; 1.0744x over previous
#include <cuda_runtime.h>
#include <cuda_fp16.h>
#include <cstdint>

// CuGraphSAGEConv pipeline (3 kernels, plain fp16 HMMA):
//   K0 convert: x(f32) -> g_xh(fp16) [4x unrolled]; W(f32) -> g_wh fp16
//   K1 gather:  8-lane groups, 8-edge dual-tree HADD2, f32 accum -> g_agg fp16
//   K2 gemm:    128-node tiles, double-buffered cp.async (A from g_agg+g_xh),
//               single-pass mma.sync f16, fp32 accum, +bias

#define D_IN  64
#define DK    128
#define D_OUT 64

#define NPAD  100352
__device__ unsigned char g_agg[(size_t)NPAD * 128];   // fp16 agg row (128B)
__device__ __half        g_xh[(size_t)NPAD * D_IN];   // fp16 x row (128B)
__device__ unsigned char g_wh[64 * 256];              // fp16 W row (256B)

// ======================= helpers =======================
__device__ __forceinline__ uint32_t smem_u32(const void* p) {
    uint32_t a;
    asm("{ .reg .u64 t; cvta.to.shared.u64 t, %1; cvt.u32.u64 %0, t; }"
        : "=r"(a) : "l"(p));
    return a;
}
__device__ __forceinline__ void ldm_x4(uint4& r, uint32_t addr) {
    asm volatile("ldmatrix.sync.aligned.m8n8.x4.shared.b16 {%0,%1,%2,%3}, [%4];"
                 : "=r"(r.x), "=r"(r.y), "=r"(r.z), "=r"(r.w) : "r"(addr));
}
__device__ __forceinline__ void mma16816h(float* c, const uint4& a,
                                          uint32_t b0, uint32_t b1) {
    asm volatile(
        "mma.sync.aligned.m16n8k16.row.col.f32.f16.f16.f32 "
        "{%0,%1,%2,%3}, {%4,%5,%6,%7}, {%8,%9}, {%0,%1,%2,%3};"
        : "+f"(c[0]), "+f"(c[1]), "+f"(c[2]), "+f"(c[3])
        : "r"(a.x), "r"(a.y), "r"(a.z), "r"(a.w), "r"(b0), "r"(b1));
}
__device__ __forceinline__ void cp16(uint32_t dst, const void* src) {
    asm volatile("cp.async.cg.shared.global [%0], [%1], 16;"
                 :: "r"(dst), "l"(src));
}
__device__ __forceinline__ __half2 u2h(uint32_t u) {
    return *reinterpret_cast<__half2*>(&u);
}
__device__ __forceinline__ void tree4(float* acc, const uint4& v0, const uint4& v1,
                                      const uint4& v2, const uint4& v3) {
    __half2 s0 = __hadd2(__hadd2(u2h(v0.x), u2h(v1.x)), __hadd2(u2h(v2.x), u2h(v3.x)));
    __half2 s1 = __hadd2(__hadd2(u2h(v0.y), u2h(v1.y)), __hadd2(u2h(v2.y), u2h(v3.y)));
    __half2 s2 = __hadd2(__hadd2(u2h(v0.z), u2h(v1.z)), __hadd2(u2h(v2.z), u2h(v3.z)));
    __half2 s3 = __hadd2(__hadd2(u2h(v0.w), u2h(v1.w)), __hadd2(u2h(v2.w), u2h(v3.w)));
    float2 f;
    f = __half22float2(s0); acc[0] += f.x; acc[1] += f.y;
    f = __half22float2(s1); acc[2] += f.x; acc[3] += f.y;
    f = __half22float2(s2); acc[4] += f.x; acc[5] += f.y;
    f = __half22float2(s3); acc[6] += f.x; acc[7] += f.y;
}

// ======================= K0: convert x and W =======================
#define XCBLK 1568   // x blocks: 1568*256*4 >= 1.6M float4

__global__ __launch_bounds__(256)
void convert_kernel(const float4* __restrict__ x4,
                    const float4* __restrict__ W4, int nx)
{
    const int tid = threadIdx.x;
    if (blockIdx.x >= XCBLK) {
        // W path: 4 blocks x 256 = 1024 chunks = 64 o x 16 q
        const int c = (blockIdx.x - XCBLK) * 256 + tid;
        const int o = c >> 4;
        const int q = c & 15;
        float4 v0 = __ldg(W4 + o * 32 + q * 2);
        float4 v1 = __ldg(W4 + o * 32 + q * 2 + 1);
        __half2 h0 = __floats2half2_rn(v0.x, v0.y);
        __half2 h1 = __floats2half2_rn(v0.z, v0.w);
        __half2 h2 = __floats2half2_rn(v1.x, v1.y);
        __half2 h3 = __floats2half2_rn(v1.z, v1.w);
        uint4 p = make_uint4(*reinterpret_cast<uint32_t*>(&h0),
                             *reinterpret_cast<uint32_t*>(&h1),
                             *reinterpret_cast<uint32_t*>(&h2),
                             *reinterpret_cast<uint32_t*>(&h3));
        *reinterpret_cast<uint4*>(g_wh + (size_t)o * 256 + q * 16) = p;
        return;
    }
    // x path: 4 elements per thread, grid-strided for coalescing + MLP
    const int stride = XCBLK * 256;
    const int i0 = blockIdx.x * 256 + tid;
    #pragma unroll
    for (int j = 0; j < 4; j++) {
        const int i = i0 + j * stride;
        if (i < nx) {
            float4 v = __ldg(x4 + i);
            __half2 h01 = __floats2half2_rn(v.x, v.y);
            __half2 h23 = __floats2half2_rn(v.z, v.w);
            uint2 hp;
            hp.x = *reinterpret_cast<uint32_t*>(&h01);
            hp.y = *reinterpret_cast<uint32_t*>(&h23);
            reinterpret_cast<uint2*>(g_xh)[i] = hp;
        }
    }
}

// ======================= K1: gather =======================
__global__ __launch_bounds__(256)
void gather_kernel(const int* __restrict__ row,
                   const int* __restrict__ colptr,
                   int N)
{
    const int g  = (blockIdx.x * 256 + threadIdx.x) >> 3;
    const int gl = threadIdx.x & 7;
    if (g >= N) return;

    const uint4* xh4 = reinterpret_cast<const uint4*>(g_xh);

    const int e0 = __ldg(colptr + g);
    const int e1 = __ldg(colptr + g + 1);

    float acc[8];
    #pragma unroll
    for (int i = 0; i < 8; i++) acc[i] = 0.f;

    int e = e0;
    if (e + 8 <= e1) {
        int s[8];
        #pragma unroll
        for (int j = 0; j < 8; j++) s[j] = __ldg(row + e + j);
        e += 8;
        while (true) {
            const bool more = (e + 8 <= e1);
            int t[8];
            if (more) {
                #pragma unroll
                for (int j = 0; j < 8; j++) t[j] = __ldg(row + e + j);
            }
            uint4 v0 = __ldg(xh4 + (size_t)s[0] * 8 + gl);
            uint4 v1 = __ldg(xh4 + (size_t)s[1] * 8 + gl);
            uint4 v2 = __ldg(xh4 + (size_t)s[2] * 8 + gl);
            uint4 v3 = __ldg(xh4 + (size_t)s[3] * 8 + gl);
            uint4 v4 = __ldg(xh4 + (size_t)s[4] * 8 + gl);
            uint4 v5 = __ldg(xh4 + (size_t)s[5] * 8 + gl);
            uint4 v6 = __ldg(xh4 + (size_t)s[6] * 8 + gl);
            uint4 v7 = __ldg(xh4 + (size_t)s[7] * 8 + gl);
            tree4(acc, v0, v1, v2, v3);
            tree4(acc, v4, v5, v6, v7);
            if (!more) break;
            #pragma unroll
            for (int j = 0; j < 8; j++) s[j] = t[j];
            e += 8;
        }
    }
    if (e + 4 <= e1) {
        int s0 = __ldg(row + e), s1 = __ldg(row + e + 1);
        int s2 = __ldg(row + e + 2), s3 = __ldg(row + e + 3);
        uint4 v0 = __ldg(xh4 + (size_t)s0 * 8 + gl);
        uint4 v1 = __ldg(xh4 + (size_t)s1 * 8 + gl);
        uint4 v2 = __ldg(xh4 + (size_t)s2 * 8 + gl);
        uint4 v3 = __ldg(xh4 + (size_t)s3 * 8 + gl);
        tree4(acc, v0, v1, v2, v3);
        e += 4;
    }
    for (; e < e1; e++) {
        int s = __ldg(row + e);
        uint4 v = __ldg(xh4 + (size_t)s * 8 + gl);
        float2 f;
        f = __half22float2(u2h(v.x)); acc[0] += f.x; acc[1] += f.y;
        f = __half22float2(u2h(v.y)); acc[2] += f.x; acc[3] += f.y;
        f = __half22float2(u2h(v.z)); acc[4] += f.x; acc[5] += f.y;
        f = __half22float2(u2h(v.w)); acc[6] += f.x; acc[7] += f.y;
    }

    const int deg = e1 - e0;
    const float inv = 1.f / (float)(deg > 0 ? deg : 1);
    #pragma unroll
    for (int i = 0; i < 8; i++) acc[i] *= inv;

    __half2 h0 = __floats2half2_rn(acc[0], acc[1]);
    __half2 h1 = __floats2half2_rn(acc[2], acc[3]);
    __half2 h2 = __floats2half2_rn(acc[4], acc[5]);
    __half2 h3 = __floats2half2_rn(acc[6], acc[7]);
    uint4 o4 = make_uint4(*reinterpret_cast<uint32_t*>(&h0),
                          *reinterpret_cast<uint32_t*>(&h1),
                          *reinterpret_cast<uint32_t*>(&h2),
                          *reinterpret_cast<uint32_t*>(&h3));
    *reinterpret_cast<uint4*>(g_agg + (size_t)g * 128 + gl * 16) = o4;
}

// ======================= K2: pipelined HMMA GEMM =======================
#define TB     128       // nodes per tile
#define ROWB   272
#define SM_WHI 0         // 64 rows x 272B = 17408
#define SM_A0  17408     // A buffer 0: 128 rows x 272B = 34816
#define SM_A1  52224     // A buffer 1
#define SM_TOT 87040
#define GRID2  296

extern __shared__ char g_sm[];

__device__ __forceinline__ void stage_tile(uint32_t sb, int buf, int tbase, int tid)
{
    const uint32_t abase = sb + (buf ? SM_A1 : SM_A0);
    #pragma unroll
    for (int j = 0; j < 8; j++) {
        const int c = tid + 256 * j;        // 0..2047
        const int r = c >> 4;               // row 0..127
        const int q = c & 15;               // chunk: 0..7 agg, 8..15 x
        const unsigned char* src = (q < 8)
            ? g_agg + (size_t)(tbase + r) * 128 + q * 16
            : reinterpret_cast<const unsigned char*>(g_xh)
              + (size_t)(tbase + r) * 128 + (q - 8) * 16;
        cp16(abase + r * ROWB + q * 16, src);
    }
    asm volatile("cp.async.commit_group;" ::: "memory");
}

__global__ __launch_bounds__(256, 2)
void gemm_mma_kernel(const float* __restrict__ b,
                     float*       __restrict__ out,
                     int N, int ntiles)
{
    const uint32_t sb = smem_u32(g_sm);
    const int tid  = threadIdx.x;
    const int wid  = tid >> 5;
    const int lane = tid & 31;

    // ---- stage W (once per block): 1024 chunks ----
    #pragma unroll
    for (int j = 0; j < 4; j++) {
        const int c = tid + 256 * j;        // 0..1023
        const int o = c >> 4;
        const int q = c & 15;
        cp16(sb + SM_WHI + o * ROWB + q * 16, g_wh + (size_t)o * 256 + q * 16);
    }
    asm volatile("cp.async.commit_group;" ::: "memory");

    int t0 = blockIdx.x;
    if (t0 < ntiles) stage_tile(sb, 0, t0 * TB, tid);

    // warp grid: 4 m-warps (32 nodes each) x 2 n-warps (32 cols each)
    const int wm = wid >> 1;
    const int wn = wid & 1;

    const uint32_t a_off = (uint32_t)(wm * 32 + (lane & 15)) * ROWB
                           + (uint32_t)(lane >> 4) * 16;
    const int brow = wn * 32 + ((lane >> 4) << 3) + (lane & 7);
    const uint32_t b_base = sb + SM_WHI
        + (uint32_t)brow * ROWB + (uint32_t)((lane >> 3) & 1) * 16;

    const int g   = lane >> 2;
    const int tig = lane & 3;
    float2 bb[4];
    #pragma unroll
    for (int ns = 0; ns < 4; ns++) {
        int col = wn * 32 + ns * 8 + 2 * tig;
        bb[ns] = make_float2(__ldg(b + col), __ldg(b + col + 1));
    }

    int i = 0;
    for (int t = t0; t < ntiles; t += GRID2, i++) {
        const int nxt = t + GRID2;
        if (nxt < ntiles) {
            stage_tile(sb, (i + 1) & 1, nxt * TB, tid);
            asm volatile("cp.async.wait_group 1;" ::: "memory");
        } else {
            asm volatile("cp.async.wait_group 0;" ::: "memory");
        }
        __syncthreads();

        const uint32_t a_base = sb + ((i & 1) ? SM_A1 : SM_A0) + a_off;

        float acc[2][4][4];
        #pragma unroll
        for (int ms = 0; ms < 2; ms++)
            #pragma unroll
            for (int ns = 0; ns < 4; ns++)
                #pragma unroll
                for (int q = 0; q < 4; q++) acc[ms][ns][q] = 0.f;

        #pragma unroll
        for (int ks = 0; ks < 8; ks++) {
            const uint32_t ao = a_base + ks * 32;
            const uint32_t bo = b_base + ks * 32;
            uint4 ah0, ah1, bh0, bh1;
            ldm_x4(ah0, ao);
            ldm_x4(ah1, ao + 16 * ROWB);
            ldm_x4(bh0, bo);
            ldm_x4(bh1, bo + 16 * ROWB);

            mma16816h(acc[0][0], ah0, bh0.x, bh0.y);
            mma16816h(acc[0][1], ah0, bh0.z, bh0.w);
            mma16816h(acc[0][2], ah0, bh1.x, bh1.y);
            mma16816h(acc[0][3], ah0, bh1.z, bh1.w);
            mma16816h(acc[1][0], ah1, bh0.x, bh0.y);
            mma16816h(acc[1][1], ah1, bh0.z, bh0.w);
            mma16816h(acc[1][2], ah1, bh1.x, bh1.y);
            mma16816h(acc[1][3], ah1, bh1.z, bh1.w);
        }

        #pragma unroll
        for (int ms = 0; ms < 2; ms++) {
            const int node0 = t * TB + wm * 32 + ms * 16 + g;
            const int node1 = node0 + 8;
            #pragma unroll
            for (int ns = 0; ns < 4; ns++) {
                const int col = wn * 32 + ns * 8 + 2 * tig;
                if (node0 < N)
                    *reinterpret_cast<float2*>(out + (size_t)node0 * D_OUT + col) =
                        make_float2(acc[ms][ns][0] + bb[ns].x,
                                    acc[ms][ns][1] + bb[ns].y);
                if (node1 < N)
                    *reinterpret_cast<float2*>(out + (size_t)node1 * D_OUT + col) =
                        make_float2(acc[ms][ns][2] + bb[ns].x,
                                    acc[ms][ns][3] + bb[ns].y);
            }
        }
        __syncthreads();
    }
}

// ======================= launch =======================
extern "C" void kernel_launch(void* const* d_in, const int* in_sizes, int n_in,
                              void* d_out, int out_size)
{
    const float* x      = (const float*)d_in[0];
    const int*   row    = (const int*)  d_in[1];
    const int*   colptr = (const int*)  d_in[2];
    const float* W      = (const float*)d_in[3];
    const float* b      = (const float*)d_in[4];
    float*       out    = (float*)d_out;

    const int N = in_sizes[2] - 1;   // 100000
    const int ntiles = (N + TB - 1) / TB;

    cudaFuncSetAttribute(gemm_mma_kernel,
                         cudaFuncAttributeMaxDynamicSharedMemorySize, SM_TOT);

    const int nx = N * 16;
    convert_kernel<<<XCBLK + 4, 256>>>(
        reinterpret_cast<const float4*>(x),
        reinterpret_cast<const float4*>(W), nx);

    gather_kernel<<<(N * 8 + 255) / 256, 256>>>(row, colptr, N);

    gemm_mma_kernel<<<GRID2, 256, SM_TOT>>>(b, out, N, ntiles);
}